// round 6
// baseline (speedup 1.0000x reference)
#include <cuda_runtime.h>

#define NN   100000
#define EE   1600000
#define KIN  256
#define KOUT 128
#define NB_SCAN ((NN + 1023) / 1024)   // 98

// Scratch (allocation-free rule: __device__ globals)
__device__ float  g_featproj[NN * KOUT];   // 51.2 MB projected features
__device__ float2 g_edges[EE];             // dst-bucketed (src_bits, weight)
__device__ int    g_outcnt[NN];
__device__ int    g_incnt[NN];
__device__ int    g_scanpart[NN];
__device__ int    g_rowoff[NN + 1];
__device__ int    g_cursor[NN];
__device__ int    g_blocksum[NB_SCAN];
__device__ int    g_blockoff[NB_SCAN];

// ---------------------------------------------------------------------------
__global__ void k_init() {
    int i = blockIdx.x * blockDim.x + threadIdx.x;
    int stride = gridDim.x * blockDim.x;
    for (int j = i; j < NN; j += stride) { g_outcnt[j] = 0; g_incnt[j] = 0; }
    if (i == 0) g_rowoff[NN] = EE;
}

// ---------------------------------------------------------------------------
__global__ void k_deg(const int* __restrict__ src, const int* __restrict__ dst) {
    int i = blockIdx.x * blockDim.x + threadIdx.x;
    if (i < EE) {
        atomicAdd(&g_outcnt[src[i]], 1);
        atomicAdd(&g_incnt[dst[i]], 1);
    }
}

// ---------------------------------------------------------------------------
// Exclusive scan of in-degrees (3 kernels)
// ---------------------------------------------------------------------------
__device__ __forceinline__ int warpInclScan(int v) {
#pragma unroll
    for (int o = 1; o < 32; o <<= 1) {
        int n = __shfl_up_sync(0xFFFFFFFFu, v, o);
        if ((threadIdx.x & 31) >= o) v += n;
    }
    return v;
}

__global__ __launch_bounds__(1024) void k_scan1() {
    __shared__ int ws[32];
    int tid = threadIdx.x;
    int i = blockIdx.x * 1024 + tid;
    int lane = tid & 31, wid = tid >> 5;
    int v = (i < NN) ? g_incnt[i] : 0;
    int inc = warpInclScan(v);
    if (lane == 31) ws[wid] = inc;
    __syncthreads();
    if (wid == 0) ws[lane] = warpInclScan(ws[lane]);
    __syncthreads();
    int excl = inc - v + (wid > 0 ? ws[wid - 1] : 0);
    if (i < NN) g_scanpart[i] = excl;
    if (tid == 1023) g_blocksum[blockIdx.x] = ws[31];
}

__global__ __launch_bounds__(128) void k_scan2() {
    __shared__ int ws[4];
    int tid = threadIdx.x;
    int lane = tid & 31, wid = tid >> 5;
    int v = (tid < NB_SCAN) ? g_blocksum[tid] : 0;
    int inc = warpInclScan(v);
    if (lane == 31) ws[wid] = inc;
    __syncthreads();
    if (wid == 0) {
        int w = (lane < 4) ? ws[lane] : 0;   // full warp runs the shfl scan
        w = warpInclScan(w);
        if (lane < 4) ws[lane] = w;
    }
    __syncthreads();
    int excl = inc - v + (wid > 0 ? ws[wid - 1] : 0);
    if (tid < NB_SCAN) g_blockoff[tid] = excl;
}

__global__ void k_scan3() {
    int i = blockIdx.x * blockDim.x + threadIdx.x;
    if (i < NN) {
        int off = g_scanpart[i] + g_blockoff[i >> 10];
        g_rowoff[i] = off;
        g_cursor[i] = off;
    }
}

// ---------------------------------------------------------------------------
__global__ void k_bucket(const int* __restrict__ src, const int* __restrict__ dst,
                         const float* __restrict__ ew) {
    int e = blockIdx.x * blockDim.x + threadIdx.x;
    if (e < EE) {
        int d = dst[e];
        int pos = atomicAdd(&g_cursor[d], 1);
        g_edges[pos] = make_float2(__int_as_float(src[e]), ew[e]);
    }
}

// ---------------------------------------------------------------------------
// Kernel: FP32 SGEMM via packed fma.rn.f32x2, ZERO pack movs:
//  - A tile stored duplicated (Asd[k][2m]==Asd[k][2m+1]) -> LDS.64 gives (a,a)
//  - B pairs loaded as ulonglong2 (LDS.128) -> packed (b0,b1),(b2,b3) for free
// BM=128, BN=128(=KOUT), BK=8, 256 threads, 8 rows x 4 packed-col-pairs/thread
// ---------------------------------------------------------------------------
__global__ __launch_bounds__(256) void k_gemm(const float* __restrict__ feat,
                                              const float* __restrict__ weight,
                                              const float* __restrict__ maskr) {
    __shared__ float Asd[8][256];   // duplicated A: [k][2m..2m+1]
    __shared__ float Bs[8][128];    // [k][n]

    const int tid = threadIdx.x;
    const int blockRow = blockIdx.x * 128;

    const int arow = tid >> 1;          // 0..127
    const int acol = (tid & 1) * 4;     // 0 or 4
    const int grow = blockRow + arow;
    float scale = 0.f;
    if (grow < NN) scale = rsqrtf((float)max(g_outcnt[grow], 1));

    const int brow = tid >> 5;
    const int bcol = (tid & 31) * 4;
    const int ty = tid >> 4;
    const int tx = tid & 15;

    unsigned long long acc2[8][4];      // acc2[i][j] = cols {2j,2j+1} of row i
#pragma unroll
    for (int i = 0; i < 8; i++)
#pragma unroll
        for (int j = 0; j < 4; j++) acc2[i][j] = 0ULL;

    for (int k0 = 0; k0 < KIN; k0 += 8) {
        float4 a = make_float4(0.f, 0.f, 0.f, 0.f);
        if (grow < NN)
            a = *reinterpret_cast<const float4*>(&feat[grow * KIN + k0 + acol]);
        a.x *= scale; a.y *= scale; a.z *= scale; a.w *= scale;
        *reinterpret_cast<float2*>(&Asd[acol + 0][2 * arow]) = make_float2(a.x, a.x);
        *reinterpret_cast<float2*>(&Asd[acol + 1][2 * arow]) = make_float2(a.y, a.y);
        *reinterpret_cast<float2*>(&Asd[acol + 2][2 * arow]) = make_float2(a.z, a.z);
        *reinterpret_cast<float2*>(&Asd[acol + 3][2 * arow]) = make_float2(a.w, a.w);

        float4 w4 = *reinterpret_cast<const float4*>(&weight[(k0 + brow) * KOUT + bcol]);
        float4 m4 = *reinterpret_cast<const float4*>(&maskr [(k0 + brow) * KOUT + bcol]);
        w4.x = (m4.x > 0.5f) ? w4.x : 0.f;
        w4.y = (m4.y > 0.5f) ? w4.y : 0.f;
        w4.z = (m4.z > 0.5f) ? w4.z : 0.f;
        w4.w = (m4.w > 0.5f) ? w4.w : 0.f;
        *reinterpret_cast<float4*>(&Bs[brow][bcol]) = w4;

        __syncthreads();

#pragma unroll
        for (int k = 0; k < 8; k++) {
            unsigned long long br2[4];
            ulonglong2 b01 = *reinterpret_cast<const ulonglong2*>(&Bs[k][tx * 8]);
            ulonglong2 b23 = *reinterpret_cast<const ulonglong2*>(&Bs[k][tx * 8 + 4]);
            br2[0] = b01.x; br2[1] = b01.y; br2[2] = b23.x; br2[3] = b23.y;

            unsigned long long ar2[8];
#pragma unroll
            for (int i = 0; i < 8; i++)
                ar2[i] = *reinterpret_cast<const unsigned long long*>(
                             &Asd[k][2 * (ty * 8 + i)]);

#pragma unroll
            for (int i = 0; i < 8; i++)
#pragma unroll
                for (int j = 0; j < 4; j++)
                    asm("fma.rn.f32x2 %0, %1, %2, %0;"
                        : "+l"(acc2[i][j]) : "l"(ar2[i]), "l"(br2[j]));
        }
        __syncthreads();
    }

#pragma unroll
    for (int i = 0; i < 8; i++) {
        int r = blockRow + ty * 8 + i;
        if (r < NN) {
            *reinterpret_cast<ulonglong2*>(&g_featproj[r * KOUT + tx * 8]) =
                make_ulonglong2(acc2[i][0], acc2[i][1]);
            *reinterpret_cast<ulonglong2*>(&g_featproj[r * KOUT + tx * 8 + 4]) =
                make_ulonglong2(acc2[i][2], acc2[i][3]);
        }
    }
}

// ---------------------------------------------------------------------------
// Kernel: aggregation. One warp per dst node, atomic-free, fused finalize.
// ---------------------------------------------------------------------------
__global__ __launch_bounds__(256) void k_agg(float* __restrict__ out,
                                             const float* __restrict__ bias) {
    int node = blockIdx.x * 8 + (threadIdx.x >> 5);
    int lane = threadIdx.x & 31;
    if (node >= NN) return;

    int beg = g_rowoff[node];
    int end = g_rowoff[node + 1];

    float4 acc = make_float4(0.f, 0.f, 0.f, 0.f);
    int e = beg;
    for (; e + 1 < end; e += 2) {
        float2 e0 = g_edges[e];
        float2 e1 = g_edges[e + 1];
        int s0 = __float_as_int(e0.x);
        int s1 = __float_as_int(e1.x);
        float4 v0 = *reinterpret_cast<const float4*>(&g_featproj[s0 * KOUT + lane * 4]);
        float4 v1 = *reinterpret_cast<const float4*>(&g_featproj[s1 * KOUT + lane * 4]);
        acc.x = fmaf(e0.y, v0.x, fmaf(e1.y, v1.x, acc.x));
        acc.y = fmaf(e0.y, v0.y, fmaf(e1.y, v1.y, acc.y));
        acc.z = fmaf(e0.y, v0.z, fmaf(e1.y, v1.z, acc.z));
        acc.w = fmaf(e0.y, v0.w, fmaf(e1.y, v1.w, acc.w));
    }
    if (e < end) {
        float2 e0 = g_edges[e];
        int s0 = __float_as_int(e0.x);
        float4 v0 = *reinterpret_cast<const float4*>(&g_featproj[s0 * KOUT + lane * 4]);
        acc.x = fmaf(e0.y, v0.x, acc.x);
        acc.y = fmaf(e0.y, v0.y, acc.y);
        acc.z = fmaf(e0.y, v0.z, acc.z);
        acc.w = fmaf(e0.y, v0.w, acc.w);
    }

    float sc = rsqrtf((float)max(end - beg, 1));
    float4 b = *reinterpret_cast<const float4*>(&bias[lane * 4]);
    acc.x = fmaf(acc.x, sc, b.x);
    acc.y = fmaf(acc.y, sc, b.y);
    acc.z = fmaf(acc.z, sc, b.z);
    acc.w = fmaf(acc.w, sc, b.w);
    *reinterpret_cast<float4*>(&out[node * KOUT + lane * 4]) = acc;
}

// ---------------------------------------------------------------------------
extern "C" void kernel_launch(void* const* d_in, const int* in_sizes, int n_in,
                              void* d_out, int out_size) {
    const float* feat   = (const float*)d_in[0];
    const int*   src    = (const int*)  d_in[1];
    const int*   dst    = (const int*)  d_in[2];
    const float* ew     = (const float*)d_in[3];
    const float* weight = (const float*)d_in[4];
    const float* bias   = (const float*)d_in[5];
    const float* maskr  = (const float*)d_in[6];
    float* out = (float*)d_out;

    k_init<<<256, 256>>>();
    k_deg<<<(EE + 255) / 256, 256>>>(src, dst);
    k_scan1<<<NB_SCAN, 1024>>>();
    k_scan2<<<1, 128>>>();
    k_scan3<<<(NN + 255) / 256, 256>>>();
    k_bucket<<<(EE + 255) / 256, 256>>>(src, dst, ew);
    k_gemm<<<(NN + 127) / 128, 256>>>(feat, weight, maskr);
    k_agg<<<(NN + 7) / 8, 256>>>(out, bias);
}

// round 7
// speedup vs baseline: 1.0047x; 1.0047x over previous
#include <cuda_runtime.h>

#define NN   100000
#define EE   1600000
#define KIN  256
#define KOUT 128
#define NB_SCAN ((NN + 1023) / 1024)   // 98

// Scratch (allocation-free rule: __device__ globals)
__device__ float  g_featproj[NN * KOUT];   // 51.2 MB projected features
__device__ float2 g_edges[EE];             // dst-bucketed (src_bits, weight)
__device__ int    g_outcnt[NN];
__device__ int    g_incnt[NN];
__device__ int    g_scanpart[NN];
__device__ int    g_rowoff[NN + 1];
__device__ int    g_cursor[NN];
__device__ int    g_blocksum[NB_SCAN];
__device__ int    g_blockoff[NB_SCAN];

// ---------------------------------------------------------------------------
__global__ void k_init() {
    int i = blockIdx.x * blockDim.x + threadIdx.x;
    int stride = gridDim.x * blockDim.x;
    for (int j = i; j < NN; j += stride) { g_outcnt[j] = 0; g_incnt[j] = 0; }
    if (i == 0) g_rowoff[NN] = EE;
}

// ---------------------------------------------------------------------------
__global__ void k_deg(const int* __restrict__ src, const int* __restrict__ dst) {
    int i = blockIdx.x * blockDim.x + threadIdx.x;
    if (i < EE) {
        atomicAdd(&g_outcnt[src[i]], 1);
        atomicAdd(&g_incnt[dst[i]], 1);
    }
}

// ---------------------------------------------------------------------------
// Exclusive scan of in-degrees (3 kernels)
// ---------------------------------------------------------------------------
__device__ __forceinline__ int warpInclScan(int v) {
#pragma unroll
    for (int o = 1; o < 32; o <<= 1) {
        int n = __shfl_up_sync(0xFFFFFFFFu, v, o);
        if ((threadIdx.x & 31) >= o) v += n;
    }
    return v;
}

__global__ __launch_bounds__(1024) void k_scan1() {
    __shared__ int ws[32];
    int tid = threadIdx.x;
    int i = blockIdx.x * 1024 + tid;
    int lane = tid & 31, wid = tid >> 5;
    int v = (i < NN) ? g_incnt[i] : 0;
    int inc = warpInclScan(v);
    if (lane == 31) ws[wid] = inc;
    __syncthreads();
    if (wid == 0) ws[lane] = warpInclScan(ws[lane]);
    __syncthreads();
    int excl = inc - v + (wid > 0 ? ws[wid - 1] : 0);
    if (i < NN) g_scanpart[i] = excl;
    if (tid == 1023) g_blocksum[blockIdx.x] = ws[31];
}

__global__ __launch_bounds__(128) void k_scan2() {
    __shared__ int ws[4];
    int tid = threadIdx.x;
    int lane = tid & 31, wid = tid >> 5;
    int v = (tid < NB_SCAN) ? g_blocksum[tid] : 0;
    int inc = warpInclScan(v);
    if (lane == 31) ws[wid] = inc;
    __syncthreads();
    if (wid == 0) {
        int w = (lane < 4) ? ws[lane] : 0;   // full warp runs the shfl scan
        w = warpInclScan(w);
        if (lane < 4) ws[lane] = w;
    }
    __syncthreads();
    int excl = inc - v + (wid > 0 ? ws[wid - 1] : 0);
    if (tid < NB_SCAN) g_blockoff[tid] = excl;
}

__global__ void k_scan3() {
    int i = blockIdx.x * blockDim.x + threadIdx.x;
    if (i < NN) {
        int off = g_scanpart[i] + g_blockoff[i >> 10];
        g_rowoff[i] = off;
        g_cursor[i] = off;
    }
}

// ---------------------------------------------------------------------------
__global__ void k_bucket(const int* __restrict__ src, const int* __restrict__ dst,
                         const float* __restrict__ ew) {
    int e = blockIdx.x * blockDim.x + threadIdx.x;
    if (e < EE) {
        int d = dst[e];
        int pos = atomicAdd(&g_cursor[d], 1);
        g_edges[pos] = make_float2(__int_as_float(src[e]), ew[e]);
    }
}

// ---------------------------------------------------------------------------
// Kernel: FP32 SGEMM via packed fma.rn.f32x2, ZERO pack movs:
//  - A tile stored duplicated (Asd[k][2m]==Asd[k][2m+1]) -> LDS.64 gives (a,a)
//  - B pairs loaded as ulonglong2 (LDS.128) -> packed (b0,b1),(b2,b3) for free
// BM=128, BN=128(=KOUT), BK=8, 256 threads, 8 rows x 4 packed-col-pairs/thread
// ---------------------------------------------------------------------------
__global__ __launch_bounds__(256) void k_gemm(const float* __restrict__ feat,
                                              const float* __restrict__ weight,
                                              const float* __restrict__ maskr) {
    __shared__ float Asd[8][256];   // duplicated A: [k][2m..2m+1]
    __shared__ float Bs[8][128];    // [k][n]

    const int tid = threadIdx.x;
    const int blockRow = blockIdx.x * 128;

    const int arow = tid >> 1;          // 0..127
    const int acol = (tid & 1) * 4;     // 0 or 4
    const int grow = blockRow + arow;
    float scale = 0.f;
    if (grow < NN) scale = rsqrtf((float)max(g_outcnt[grow], 1));

    const int brow = tid >> 5;
    const int bcol = (tid & 31) * 4;
    const int ty = tid >> 4;
    const int tx = tid & 15;

    unsigned long long acc2[8][4];      // acc2[i][j] = cols {2j,2j+1} of row i
#pragma unroll
    for (int i = 0; i < 8; i++)
#pragma unroll
        for (int j = 0; j < 4; j++) acc2[i][j] = 0ULL;

    for (int k0 = 0; k0 < KIN; k0 += 8) {
        float4 a = make_float4(0.f, 0.f, 0.f, 0.f);
        if (grow < NN)
            a = *reinterpret_cast<const float4*>(&feat[grow * KIN + k0 + acol]);
        a.x *= scale; a.y *= scale; a.z *= scale; a.w *= scale;
        *reinterpret_cast<float2*>(&Asd[acol + 0][2 * arow]) = make_float2(a.x, a.x);
        *reinterpret_cast<float2*>(&Asd[acol + 1][2 * arow]) = make_float2(a.y, a.y);
        *reinterpret_cast<float2*>(&Asd[acol + 2][2 * arow]) = make_float2(a.z, a.z);
        *reinterpret_cast<float2*>(&Asd[acol + 3][2 * arow]) = make_float2(a.w, a.w);

        float4 w4 = *reinterpret_cast<const float4*>(&weight[(k0 + brow) * KOUT + bcol]);
        float4 m4 = *reinterpret_cast<const float4*>(&maskr [(k0 + brow) * KOUT + bcol]);
        w4.x = (m4.x > 0.5f) ? w4.x : 0.f;
        w4.y = (m4.y > 0.5f) ? w4.y : 0.f;
        w4.z = (m4.z > 0.5f) ? w4.z : 0.f;
        w4.w = (m4.w > 0.5f) ? w4.w : 0.f;
        *reinterpret_cast<float4*>(&Bs[brow][bcol]) = w4;

        __syncthreads();

#pragma unroll
        for (int k = 0; k < 8; k++) {
            unsigned long long br2[4];
            ulonglong2 b01 = *reinterpret_cast<const ulonglong2*>(&Bs[k][tx * 8]);
            ulonglong2 b23 = *reinterpret_cast<const ulonglong2*>(&Bs[k][tx * 8 + 4]);
            br2[0] = b01.x; br2[1] = b01.y; br2[2] = b23.x; br2[3] = b23.y;

            unsigned long long ar2[8];
#pragma unroll
            for (int i = 0; i < 8; i++)
                ar2[i] = *reinterpret_cast<const unsigned long long*>(
                             &Asd[k][2 * (ty * 8 + i)]);

#pragma unroll
            for (int i = 0; i < 8; i++)
#pragma unroll
                for (int j = 0; j < 4; j++)
                    asm("fma.rn.f32x2 %0, %1, %2, %0;"
                        : "+l"(acc2[i][j]) : "l"(ar2[i]), "l"(br2[j]));
        }
        __syncthreads();
    }

#pragma unroll
    for (int i = 0; i < 8; i++) {
        int r = blockRow + ty * 8 + i;
        if (r < NN) {
            *reinterpret_cast<ulonglong2*>(&g_featproj[r * KOUT + tx * 8]) =
                make_ulonglong2(acc2[i][0], acc2[i][1]);
            *reinterpret_cast<ulonglong2*>(&g_featproj[r * KOUT + tx * 8 + 4]) =
                make_ulonglong2(acc2[i][2], acc2[i][3]);
        }
    }
}

// ---------------------------------------------------------------------------
// Kernel: aggregation. One warp per dst node, atomic-free, fused finalize.
// ---------------------------------------------------------------------------
__global__ __launch_bounds__(256) void k_agg(float* __restrict__ out,
                                             const float* __restrict__ bias) {
    int node = blockIdx.x * 8 + (threadIdx.x >> 5);
    int lane = threadIdx.x & 31;
    if (node >= NN) return;

    int beg = g_rowoff[node];
    int end = g_rowoff[node + 1];

    float4 acc = make_float4(0.f, 0.f, 0.f, 0.f);
    int e = beg;
    for (; e + 1 < end; e += 2) {
        float2 e0 = g_edges[e];
        float2 e1 = g_edges[e + 1];
        int s0 = __float_as_int(e0.x);
        int s1 = __float_as_int(e1.x);
        float4 v0 = *reinterpret_cast<const float4*>(&g_featproj[s0 * KOUT + lane * 4]);
        float4 v1 = *reinterpret_cast<const float4*>(&g_featproj[s1 * KOUT + lane * 4]);
        acc.x = fmaf(e0.y, v0.x, fmaf(e1.y, v1.x, acc.x));
        acc.y = fmaf(e0.y, v0.y, fmaf(e1.y, v1.y, acc.y));
        acc.z = fmaf(e0.y, v0.z, fmaf(e1.y, v1.z, acc.z));
        acc.w = fmaf(e0.y, v0.w, fmaf(e1.y, v1.w, acc.w));
    }
    if (e < end) {
        float2 e0 = g_edges[e];
        int s0 = __float_as_int(e0.x);
        float4 v0 = *reinterpret_cast<const float4*>(&g_featproj[s0 * KOUT + lane * 4]);
        acc.x = fmaf(e0.y, v0.x, acc.x);
        acc.y = fmaf(e0.y, v0.y, acc.y);
        acc.z = fmaf(e0.y, v0.z, acc.z);
        acc.w = fmaf(e0.y, v0.w, acc.w);
    }

    float sc = rsqrtf((float)max(end - beg, 1));
    float4 b = *reinterpret_cast<const float4*>(&bias[lane * 4]);
    acc.x = fmaf(acc.x, sc, b.x);
    acc.y = fmaf(acc.y, sc, b.y);
    acc.z = fmaf(acc.z, sc, b.z);
    acc.w = fmaf(acc.w, sc, b.w);
    *reinterpret_cast<float4*>(&out[node * KOUT + lane * 4]) = acc;
}

// ---------------------------------------------------------------------------
extern "C" void kernel_launch(void* const* d_in, const int* in_sizes, int n_in,
                              void* d_out, int out_size) {
    const float* feat   = (const float*)d_in[0];
    const int*   src    = (const int*)  d_in[1];
    const int*   dst    = (const int*)  d_in[2];
    const float* ew     = (const float*)d_in[3];
    const float* weight = (const float*)d_in[4];
    const float* bias   = (const float*)d_in[5];
    const float* maskr  = (const float*)d_in[6];
    float* out = (float*)d_out;

    k_init<<<256, 256>>>();
    k_deg<<<(EE + 255) / 256, 256>>>(src, dst);
    k_scan1<<<NB_SCAN, 1024>>>();
    k_scan2<<<1, 128>>>();
    k_scan3<<<(NN + 255) / 256, 256>>>();
    k_bucket<<<(EE + 255) / 256, 256>>>(src, dst, ew);
    k_gemm<<<(NN + 127) / 128, 256>>>(feat, weight, maskr);
    k_agg<<<(NN + 7) / 8, 256>>>(out, bias);
}

// round 8
// speedup vs baseline: 1.0068x; 1.0020x over previous
#include <cuda_runtime.h>

#define NN   100000
#define EE   1600000
#define KIN  256
#define KOUT 128
#define NB_SCAN ((NN + 1023) / 1024)   // 98

// Scratch (allocation-free rule: __device__ globals)
__device__ float  g_featproj[NN * KOUT];   // 51.2 MB projected features
__device__ float2 g_edges[EE];             // dst-bucketed (src_bits, weight)
__device__ int    g_outcnt[NN];
__device__ int    g_incnt[NN];
__device__ int    g_scanpart[NN];
__device__ int    g_rowoff[NN + 1];
__device__ int    g_cursor[NN];
__device__ int    g_blocksum[NB_SCAN];
__device__ int    g_blockoff[NB_SCAN];

// ---------------------------------------------------------------------------
__global__ void k_init() {
    int i = blockIdx.x * blockDim.x + threadIdx.x;
    int stride = gridDim.x * blockDim.x;
    for (int j = i; j < NN; j += stride) { g_outcnt[j] = 0; g_incnt[j] = 0; }
    if (i == 0) g_rowoff[NN] = EE;
}

// ---------------------------------------------------------------------------
__global__ void k_deg(const int* __restrict__ src, const int* __restrict__ dst) {
    int i = blockIdx.x * blockDim.x + threadIdx.x;
    if (i < EE) {
        atomicAdd(&g_outcnt[src[i]], 1);
        atomicAdd(&g_incnt[dst[i]], 1);
    }
}

// ---------------------------------------------------------------------------
// Exclusive scan of in-degrees (3 kernels)
// ---------------------------------------------------------------------------
__device__ __forceinline__ int warpInclScan(int v) {
#pragma unroll
    for (int o = 1; o < 32; o <<= 1) {
        int n = __shfl_up_sync(0xFFFFFFFFu, v, o);
        if ((threadIdx.x & 31) >= o) v += n;
    }
    return v;
}

__global__ __launch_bounds__(1024) void k_scan1() {
    __shared__ int ws[32];
    int tid = threadIdx.x;
    int i = blockIdx.x * 1024 + tid;
    int lane = tid & 31, wid = tid >> 5;
    int v = (i < NN) ? g_incnt[i] : 0;
    int inc = warpInclScan(v);
    if (lane == 31) ws[wid] = inc;
    __syncthreads();
    if (wid == 0) ws[lane] = warpInclScan(ws[lane]);
    __syncthreads();
    int excl = inc - v + (wid > 0 ? ws[wid - 1] : 0);
    if (i < NN) g_scanpart[i] = excl;
    if (tid == 1023) g_blocksum[blockIdx.x] = ws[31];
}

__global__ __launch_bounds__(128) void k_scan2() {
    __shared__ int ws[4];
    int tid = threadIdx.x;
    int lane = tid & 31, wid = tid >> 5;
    int v = (tid < NB_SCAN) ? g_blocksum[tid] : 0;
    int inc = warpInclScan(v);
    if (lane == 31) ws[wid] = inc;
    __syncthreads();
    if (wid == 0) {
        int w = (lane < 4) ? ws[lane] : 0;   // full warp runs the shfl scan
        w = warpInclScan(w);
        if (lane < 4) ws[lane] = w;
    }
    __syncthreads();
    int excl = inc - v + (wid > 0 ? ws[wid - 1] : 0);
    if (tid < NB_SCAN) g_blockoff[tid] = excl;
}

__global__ void k_scan3() {
    int i = blockIdx.x * blockDim.x + threadIdx.x;
    if (i < NN) {
        int off = g_scanpart[i] + g_blockoff[i >> 10];
        g_rowoff[i] = off;
        g_cursor[i] = off;
    }
}

// ---------------------------------------------------------------------------
__global__ void k_bucket(const int* __restrict__ src, const int* __restrict__ dst,
                         const float* __restrict__ ew) {
    int e = blockIdx.x * blockDim.x + threadIdx.x;
    if (e < EE) {
        int d = dst[e];
        int pos = atomicAdd(&g_cursor[d], 1);
        g_edges[pos] = make_float2(__int_as_float(src[e]), ew[e]);
    }
}

// ---------------------------------------------------------------------------
// Kernel: FP32 SGEMM via packed fma.rn.f32x2, ZERO pack movs:
//  - A tile stored duplicated (Asd[k][2m]==Asd[k][2m+1]) -> LDS.64 gives (a,a)
//  - B pairs loaded as ulonglong2 (LDS.128) -> packed (b0,b1),(b2,b3) for free
// BM=128, BN=128(=KOUT), BK=8, 256 threads, 8 rows x 4 packed-col-pairs/thread
// ---------------------------------------------------------------------------
__global__ __launch_bounds__(256) void k_gemm(const float* __restrict__ feat,
                                              const float* __restrict__ weight,
                                              const float* __restrict__ maskr) {
    __shared__ float Asd[8][256];   // duplicated A: [k][2m..2m+1]
    __shared__ float Bs[8][128];    // [k][n]

    const int tid = threadIdx.x;
    const int blockRow = blockIdx.x * 128;

    const int arow = tid >> 1;          // 0..127
    const int acol = (tid & 1) * 4;     // 0 or 4
    const int grow = blockRow + arow;
    float scale = 0.f;
    if (grow < NN) scale = rsqrtf((float)max(g_outcnt[grow], 1));

    const int brow = tid >> 5;
    const int bcol = (tid & 31) * 4;
    const int ty = tid >> 4;
    const int tx = tid & 15;

    unsigned long long acc2[8][4];      // acc2[i][j] = cols {2j,2j+1} of row i
#pragma unroll
    for (int i = 0; i < 8; i++)
#pragma unroll
        for (int j = 0; j < 4; j++) acc2[i][j] = 0ULL;

    for (int k0 = 0; k0 < KIN; k0 += 8) {
        float4 a = make_float4(0.f, 0.f, 0.f, 0.f);
        if (grow < NN)
            a = *reinterpret_cast<const float4*>(&feat[grow * KIN + k0 + acol]);
        a.x *= scale; a.y *= scale; a.z *= scale; a.w *= scale;
        *reinterpret_cast<float2*>(&Asd[acol + 0][2 * arow]) = make_float2(a.x, a.x);
        *reinterpret_cast<float2*>(&Asd[acol + 1][2 * arow]) = make_float2(a.y, a.y);
        *reinterpret_cast<float2*>(&Asd[acol + 2][2 * arow]) = make_float2(a.z, a.z);
        *reinterpret_cast<float2*>(&Asd[acol + 3][2 * arow]) = make_float2(a.w, a.w);

        float4 w4 = *reinterpret_cast<const float4*>(&weight[(k0 + brow) * KOUT + bcol]);
        float4 m4 = *reinterpret_cast<const float4*>(&maskr [(k0 + brow) * KOUT + bcol]);
        w4.x = (m4.x > 0.5f) ? w4.x : 0.f;
        w4.y = (m4.y > 0.5f) ? w4.y : 0.f;
        w4.z = (m4.z > 0.5f) ? w4.z : 0.f;
        w4.w = (m4.w > 0.5f) ? w4.w : 0.f;
        *reinterpret_cast<float4*>(&Bs[brow][bcol]) = w4;

        __syncthreads();

#pragma unroll
        for (int k = 0; k < 8; k++) {
            unsigned long long br2[4];
            ulonglong2 b01 = *reinterpret_cast<const ulonglong2*>(&Bs[k][tx * 8]);
            ulonglong2 b23 = *reinterpret_cast<const ulonglong2*>(&Bs[k][tx * 8 + 4]);
            br2[0] = b01.x; br2[1] = b01.y; br2[2] = b23.x; br2[3] = b23.y;

            unsigned long long ar2[8];
#pragma unroll
            for (int i = 0; i < 8; i++)
                ar2[i] = *reinterpret_cast<const unsigned long long*>(
                             &Asd[k][2 * (ty * 8 + i)]);

#pragma unroll
            for (int i = 0; i < 8; i++)
#pragma unroll
                for (int j = 0; j < 4; j++)
                    asm("fma.rn.f32x2 %0, %1, %2, %0;"
                        : "+l"(acc2[i][j]) : "l"(ar2[i]), "l"(br2[j]));
        }
        __syncthreads();
    }

#pragma unroll
    for (int i = 0; i < 8; i++) {
        int r = blockRow + ty * 8 + i;
        if (r < NN) {
            *reinterpret_cast<ulonglong2*>(&g_featproj[r * KOUT + tx * 8]) =
                make_ulonglong2(acc2[i][0], acc2[i][1]);
            *reinterpret_cast<ulonglong2*>(&g_featproj[r * KOUT + tx * 8 + 4]) =
                make_ulonglong2(acc2[i][2], acc2[i][3]);
        }
    }
}

// ---------------------------------------------------------------------------
// Kernel: aggregation. One warp per dst node, atomic-free, fused finalize.
// ---------------------------------------------------------------------------
__global__ __launch_bounds__(256) void k_agg(float* __restrict__ out,
                                             const float* __restrict__ bias) {
    int node = blockIdx.x * 8 + (threadIdx.x >> 5);
    int lane = threadIdx.x & 31;
    if (node >= NN) return;

    int beg = g_rowoff[node];
    int end = g_rowoff[node + 1];

    float4 acc = make_float4(0.f, 0.f, 0.f, 0.f);
    int e = beg;
    for (; e + 1 < end; e += 2) {
        float2 e0 = g_edges[e];
        float2 e1 = g_edges[e + 1];
        int s0 = __float_as_int(e0.x);
        int s1 = __float_as_int(e1.x);
        float4 v0 = *reinterpret_cast<const float4*>(&g_featproj[s0 * KOUT + lane * 4]);
        float4 v1 = *reinterpret_cast<const float4*>(&g_featproj[s1 * KOUT + lane * 4]);
        acc.x = fmaf(e0.y, v0.x, fmaf(e1.y, v1.x, acc.x));
        acc.y = fmaf(e0.y, v0.y, fmaf(e1.y, v1.y, acc.y));
        acc.z = fmaf(e0.y, v0.z, fmaf(e1.y, v1.z, acc.z));
        acc.w = fmaf(e0.y, v0.w, fmaf(e1.y, v1.w, acc.w));
    }
    if (e < end) {
        float2 e0 = g_edges[e];
        int s0 = __float_as_int(e0.x);
        float4 v0 = *reinterpret_cast<const float4*>(&g_featproj[s0 * KOUT + lane * 4]);
        acc.x = fmaf(e0.y, v0.x, acc.x);
        acc.y = fmaf(e0.y, v0.y, acc.y);
        acc.z = fmaf(e0.y, v0.z, acc.z);
        acc.w = fmaf(e0.y, v0.w, acc.w);
    }

    float sc = rsqrtf((float)max(end - beg, 1));
    float4 b = *reinterpret_cast<const float4*>(&bias[lane * 4]);
    acc.x = fmaf(acc.x, sc, b.x);
    acc.y = fmaf(acc.y, sc, b.y);
    acc.z = fmaf(acc.z, sc, b.z);
    acc.w = fmaf(acc.w, sc, b.w);
    *reinterpret_cast<float4*>(&out[node * KOUT + lane * 4]) = acc;
}

// ---------------------------------------------------------------------------
extern "C" void kernel_launch(void* const* d_in, const int* in_sizes, int n_in,
                              void* d_out, int out_size) {
    const float* feat   = (const float*)d_in[0];
    const int*   src    = (const int*)  d_in[1];
    const int*   dst    = (const int*)  d_in[2];
    const float* ew     = (const float*)d_in[3];
    const float* weight = (const float*)d_in[4];
    const float* bias   = (const float*)d_in[5];
    const float* maskr  = (const float*)d_in[6];
    float* out = (float*)d_out;

    k_init<<<256, 256>>>();
    k_deg<<<(EE + 255) / 256, 256>>>(src, dst);
    k_scan1<<<NB_SCAN, 1024>>>();
    k_scan2<<<1, 128>>>();
    k_scan3<<<(NN + 255) / 256, 256>>>();
    k_bucket<<<(EE + 255) / 256, 256>>>(src, dst, ew);
    k_gemm<<<(NN + 127) / 128, 256>>>(feat, weight, maskr);
    k_agg<<<(NN + 7) / 8, 256>>>(out, bias);
}

// round 10
// speedup vs baseline: 1.7171x; 1.7055x over previous
#include <cuda_runtime.h>
#include <cuda_bf16.h>
#include <cstdint>

#define NN   100000
#define EE   1600000
#define KIN  256
#define KOUT 128
#define NB_SCAN ((NN + 1023) / 1024)   // 98

// Scratch (allocation-free rule: __device__ globals)
__device__ float  g_featproj[NN * KOUT];   // 51.2 MB projected features
__device__ float2 g_edges[EE];             // dst-bucketed (src_bits, weight)
__device__ int    g_outcnt[NN];
__device__ int    g_incnt[NN];
__device__ int    g_scanpart[NN];
__device__ int    g_rowoff[NN + 1];
__device__ int    g_cursor[NN];
__device__ int    g_blocksum[NB_SCAN];
__device__ int    g_blockoff[NB_SCAN];
__device__ __nv_bfloat16 g_wt_hi[KOUT * KIN];   // W^T hi  [N=128][K=256]
__device__ __nv_bfloat16 g_wt_lo[KOUT * KIN];   // W^T lo

// ---------------------------------------------------------------------------
__global__ void k_init() {
    int i = blockIdx.x * blockDim.x + threadIdx.x;
    int stride = gridDim.x * blockDim.x;
    for (int j = i; j < NN; j += stride) { g_outcnt[j] = 0; g_incnt[j] = 0; }
    if (i == 0) g_rowoff[NN] = EE;
}

// ---------------------------------------------------------------------------
__global__ void k_deg(const int* __restrict__ src, const int* __restrict__ dst) {
    int i = blockIdx.x * blockDim.x + threadIdx.x;
    if (i < EE) {
        atomicAdd(&g_outcnt[src[i]], 1);
        atomicAdd(&g_incnt[dst[i]], 1);
    }
}

// ---------------------------------------------------------------------------
// Exclusive scan of in-degrees (3 kernels)
// ---------------------------------------------------------------------------
__device__ __forceinline__ int warpInclScan(int v) {
#pragma unroll
    for (int o = 1; o < 32; o <<= 1) {
        int n = __shfl_up_sync(0xFFFFFFFFu, v, o);
        if ((threadIdx.x & 31) >= o) v += n;
    }
    return v;
}

__global__ __launch_bounds__(1024) void k_scan1() {
    __shared__ int ws[32];
    int tid = threadIdx.x;
    int i = blockIdx.x * 1024 + tid;
    int lane = tid & 31, wid = tid >> 5;
    int v = (i < NN) ? g_incnt[i] : 0;
    int inc = warpInclScan(v);
    if (lane == 31) ws[wid] = inc;
    __syncthreads();
    if (wid == 0) ws[lane] = warpInclScan(ws[lane]);
    __syncthreads();
    int excl = inc - v + (wid > 0 ? ws[wid - 1] : 0);
    if (i < NN) g_scanpart[i] = excl;
    if (tid == 1023) g_blocksum[blockIdx.x] = ws[31];
}

__global__ __launch_bounds__(128) void k_scan2() {
    __shared__ int ws[4];
    int tid = threadIdx.x;
    int lane = tid & 31, wid = tid >> 5;
    int v = (tid < NB_SCAN) ? g_blocksum[tid] : 0;
    int inc = warpInclScan(v);
    if (lane == 31) ws[wid] = inc;
    __syncthreads();
    if (wid == 0) {
        int w = (lane < 4) ? ws[lane] : 0;   // full warp runs the shfl scan
        w = warpInclScan(w);
        if (lane < 4) ws[lane] = w;
    }
    __syncthreads();
    int excl = inc - v + (wid > 0 ? ws[wid - 1] : 0);
    if (tid < NB_SCAN) g_blockoff[tid] = excl;
}

__global__ void k_scan3() {
    int i = blockIdx.x * blockDim.x + threadIdx.x;
    if (i < NN) {
        int off = g_scanpart[i] + g_blockoff[i >> 10];
        g_rowoff[i] = off;
        g_cursor[i] = off;
    }
}

// ---------------------------------------------------------------------------
__global__ void k_bucket(const int* __restrict__ src, const int* __restrict__ dst,
                         const float* __restrict__ ew) {
    int e = blockIdx.x * blockDim.x + threadIdx.x;
    if (e < EE) {
        int d = dst[e];
        int pos = atomicAdd(&g_cursor[d], 1);
        g_edges[pos] = make_float2(__int_as_float(src[e]), ew[e]);
    }
}

// ---------------------------------------------------------------------------
// Kernel: transpose + mask + bf16 hi/lo split of the weight: W[K,N] -> Wt[N,K]
// ---------------------------------------------------------------------------
__global__ void k_wt(const float* __restrict__ weight, const float* __restrict__ maskr) {
    int i = blockIdx.x * blockDim.x + threadIdx.x;
    if (i >= KOUT * KIN) return;
    int n = i >> 8;          // 0..127
    int k = i & 255;         // 0..255
    float v = (maskr[k * KOUT + n] > 0.5f) ? weight[k * KOUT + n] : 0.f;
    __nv_bfloat16 hi = __float2bfloat16(v);
    float lo = v - __bfloat162float(hi);
    g_wt_hi[i] = hi;
    g_wt_lo[i] = __float2bfloat16(lo);
}

// ---------------------------------------------------------------------------
// bf16-split tensor-core GEMM on mma.sync (HMMA, baseline PTX — sm_103 ok).
// g_featproj = diag(out_deg^-1/2)*feat @ maskedW via Ahi*Bhi + Ahi*Blo + Alo*Bhi.
// BM=128, BN=128, BK=32; 8 warps, warp tile 32x64 (2x8 m16n8k16 tiles).
// Shared tiles padded to stride 40 bf16 (80B): conflict-free for ldmatrix.
// ---------------------------------------------------------------------------
#define SSTR 40

__device__ __forceinline__ uint32_t smem_u32(const void* p) {
    uint32_t a;
    asm("{ .reg .u64 t; cvta.to.shared.u64 t, %1; cvt.u32.u64 %0, t; }"
        : "=r"(a) : "l"(p));
    return a;
}

__device__ __forceinline__ void ldm_x4(uint32_t* r, uint32_t addr) {
    asm volatile("ldmatrix.sync.aligned.m8n8.x4.shared.b16 {%0,%1,%2,%3}, [%4];"
                 : "=r"(r[0]), "=r"(r[1]), "=r"(r[2]), "=r"(r[3]) : "r"(addr));
}

__device__ __forceinline__ void mma_bf16(float* c, const uint32_t* a, const uint32_t* b) {
    asm volatile(
        "mma.sync.aligned.m16n8k16.row.col.f32.bf16.bf16.f32 "
        "{%0,%1,%2,%3}, {%4,%5,%6,%7}, {%8,%9}, {%0,%1,%2,%3};"
        : "+f"(c[0]), "+f"(c[1]), "+f"(c[2]), "+f"(c[3])
        : "r"(a[0]), "r"(a[1]), "r"(a[2]), "r"(a[3]), "r"(b[0]), "r"(b[1]));
}

__global__ __launch_bounds__(256) void k_gemm_mma(const float* __restrict__ feat) {
    __shared__ __nv_bfloat16 sAhi[128 * SSTR];
    __shared__ __nv_bfloat16 sAlo[128 * SSTR];
    __shared__ __nv_bfloat16 sBhi[128 * SSTR];
    __shared__ __nv_bfloat16 sBlo[128 * SSTR];
    __shared__ float sscale[128];

    const int tid = threadIdx.x;
    const int wid = tid >> 5, lane = tid & 31;
    const int blockRow = blockIdx.x * 128;

    if (tid < 128) {
        int r = blockRow + tid;
        sscale[tid] = (r < NN) ? rsqrtf((float)max(g_outcnt[r], 1)) : 0.f;
    }
    __syncthreads();

    const uint32_t uAhi = smem_u32(sAhi), uAlo = smem_u32(sAlo);
    const uint32_t uBhi = smem_u32(sBhi), uBlo = smem_u32(sBlo);

    // warp tile: rows mbase..mbase+31, cols nbase..nbase+63
    const int mbase = (wid & 3) * 32;
    const int nbase = (wid >> 2) * 64;

    float acc[2][8][4];
#pragma unroll
    for (int m = 0; m < 2; m++)
#pragma unroll
        for (int n = 0; n < 8; n++)
#pragma unroll
            for (int q = 0; q < 4; q++) acc[m][n][q] = 0.f;

    // ldmatrix source addresses (bytes)
    const uint32_t aoff = (uint32_t)((lane & 15) * (SSTR * 2) + (lane >> 4) * 16);
    const uint32_t boff = (uint32_t)(((lane & 7) + ((lane >> 4) << 3)) * (SSTR * 2) +
                                     (((lane >> 3) & 1) << 4));

    for (int c = 0; c < 8; c++) {
        const int k0 = c * 32;

        // ---- A: 128 rows x 32 cols fp32 -> hi/lo bf16 (thread t: row=t/2, 16 cols)
        {
            int row = tid >> 1;
            int ch = (tid & 1) * 16;
            int gr = blockRow + row;
            float s = sscale[row];
            const float4* fp = (gr < NN)
                ? reinterpret_cast<const float4*>(&feat[gr * KIN + k0 + ch]) : nullptr;
#pragma unroll
            for (int j = 0; j < 4; j++) {
                float4 a = fp ? fp[j] : make_float4(0.f, 0.f, 0.f, 0.f);
                a.x *= s; a.y *= s; a.z *= s; a.w *= s;
                __nv_bfloat162 h0{__float2bfloat16(a.x), __float2bfloat16(a.y)};
                __nv_bfloat162 h1{__float2bfloat16(a.z), __float2bfloat16(a.w)};
                __nv_bfloat162 l0{__float2bfloat16(a.x - __bfloat162float(h0.x)),
                                  __float2bfloat16(a.y - __bfloat162float(h0.y))};
                __nv_bfloat162 l1{__float2bfloat16(a.z - __bfloat162float(h1.x)),
                                  __float2bfloat16(a.w - __bfloat162float(h1.y))};
                int o = row * SSTR + ch + j * 4;
                *reinterpret_cast<__nv_bfloat162*>(&sAhi[o])     = h0;
                *reinterpret_cast<__nv_bfloat162*>(&sAhi[o + 2]) = h1;
                *reinterpret_cast<__nv_bfloat162*>(&sAlo[o])     = l0;
                *reinterpret_cast<__nv_bfloat162*>(&sAlo[o + 2]) = l1;
            }
        }
        // ---- B: Wt[n][k0..k0+31] hi/lo (thread t: row=t/2, 16 cols as 2 uint4)
        {
            int row = tid >> 1;
            int q = (tid & 1) * 2;
            uint4 h0 = *reinterpret_cast<const uint4*>(&g_wt_hi[row * KIN + k0 + q * 8]);
            uint4 h1 = *reinterpret_cast<const uint4*>(&g_wt_hi[row * KIN + k0 + (q + 1) * 8]);
            uint4 l0 = *reinterpret_cast<const uint4*>(&g_wt_lo[row * KIN + k0 + q * 8]);
            uint4 l1 = *reinterpret_cast<const uint4*>(&g_wt_lo[row * KIN + k0 + (q + 1) * 8]);
            int o = row * SSTR + q * 8;
            *reinterpret_cast<uint4*>(&sBhi[o])     = h0;
            *reinterpret_cast<uint4*>(&sBhi[o + 8]) = h1;
            *reinterpret_cast<uint4*>(&sBlo[o])     = l0;
            *reinterpret_cast<uint4*>(&sBlo[o + 8]) = l1;
        }
        __syncthreads();

#pragma unroll
        for (int ks = 0; ks < 2; ks++) {
            const uint32_t kb = (uint32_t)(ks * 16 * 2);   // byte offset of k-step

            uint32_t ahi[2][4], alo[2][4];
#pragma unroll
            for (int mt = 0; mt < 2; mt++) {
                uint32_t ab = (uint32_t)((mbase + mt * 16) * (SSTR * 2)) + kb + aoff;
                ldm_x4(ahi[mt], uAhi + ab);
                ldm_x4(alo[mt], uAlo + ab);
            }
            uint32_t bhi[8][2], blo[8][2];
#pragma unroll
            for (int p = 0; p < 4; p++) {                  // n-tile pairs
                uint32_t bb = (uint32_t)((nbase + p * 16) * (SSTR * 2)) + kb + boff;
                uint32_t r[4];
                ldm_x4(r, uBhi + bb);
                bhi[2 * p][0] = r[0]; bhi[2 * p][1] = r[1];
                bhi[2 * p + 1][0] = r[2]; bhi[2 * p + 1][1] = r[3];
                ldm_x4(r, uBlo + bb);
                blo[2 * p][0] = r[0]; blo[2 * p][1] = r[1];
                blo[2 * p + 1][0] = r[2]; blo[2 * p + 1][1] = r[3];
            }
#pragma unroll
            for (int mt = 0; mt < 2; mt++)
#pragma unroll
                for (int nt = 0; nt < 8; nt++) {
                    mma_bf16(acc[mt][nt], ahi[mt], bhi[nt]);
                    mma_bf16(acc[mt][nt], ahi[mt], blo[nt]);
                    mma_bf16(acc[mt][nt], alo[mt], bhi[nt]);
                }
        }
        __syncthreads();
    }

    // Epilogue: c-fragment rows = l/4 (+8), cols = (l%4)*2
#pragma unroll
    for (int mt = 0; mt < 2; mt++) {
        int r0 = blockRow + mbase + mt * 16 + (lane >> 2);
        int r1 = r0 + 8;
#pragma unroll
        for (int nt = 0; nt < 8; nt++) {
            int col = nbase + nt * 8 + (lane & 3) * 2;
            if (r0 < NN)
                *reinterpret_cast<float2*>(&g_featproj[r0 * KOUT + col]) =
                    make_float2(acc[mt][nt][0], acc[mt][nt][1]);
            if (r1 < NN)
                *reinterpret_cast<float2*>(&g_featproj[r1 * KOUT + col]) =
                    make_float2(acc[mt][nt][2], acc[mt][nt][3]);
        }
    }
}

// ---------------------------------------------------------------------------
// Kernel: aggregation. One warp per dst node, atomic-free, fused finalize.
// ---------------------------------------------------------------------------
__global__ __launch_bounds__(256) void k_agg(float* __restrict__ out,
                                             const float* __restrict__ bias) {
    int node = blockIdx.x * 8 + (threadIdx.x >> 5);
    int lane = threadIdx.x & 31;
    if (node >= NN) return;

    int beg = g_rowoff[node];
    int end = g_rowoff[node + 1];

    float4 acc = make_float4(0.f, 0.f, 0.f, 0.f);
    int e = beg;
    for (; e + 1 < end; e += 2) {
        float2 e0 = g_edges[e];
        float2 e1 = g_edges[e + 1];
        int s0 = __float_as_int(e0.x);
        int s1 = __float_as_int(e1.x);
        float4 v0 = *reinterpret_cast<const float4*>(&g_featproj[s0 * KOUT + lane * 4]);
        float4 v1 = *reinterpret_cast<const float4*>(&g_featproj[s1 * KOUT + lane * 4]);
        acc.x = fmaf(e0.y, v0.x, fmaf(e1.y, v1.x, acc.x));
        acc.y = fmaf(e0.y, v0.y, fmaf(e1.y, v1.y, acc.y));
        acc.z = fmaf(e0.y, v0.z, fmaf(e1.y, v1.z, acc.z));
        acc.w = fmaf(e0.y, v0.w, fmaf(e1.y, v1.w, acc.w));
    }
    if (e < end) {
        float2 e0 = g_edges[e];
        int s0 = __float_as_int(e0.x);
        float4 v0 = *reinterpret_cast<const float4*>(&g_featproj[s0 * KOUT + lane * 4]);
        acc.x = fmaf(e0.y, v0.x, acc.x);
        acc.y = fmaf(e0.y, v0.y, acc.y);
        acc.z = fmaf(e0.y, v0.z, acc.z);
        acc.w = fmaf(e0.y, v0.w, acc.w);
    }

    float sc = rsqrtf((float)max(end - beg, 1));
    float4 b = *reinterpret_cast<const float4*>(&bias[lane * 4]);
    acc.x = fmaf(acc.x, sc, b.x);
    acc.y = fmaf(acc.y, sc, b.y);
    acc.z = fmaf(acc.z, sc, b.z);
    acc.w = fmaf(acc.w, sc, b.w);
    *reinterpret_cast<float4*>(&out[node * KOUT + lane * 4]) = acc;
}

// ---------------------------------------------------------------------------
extern "C" void kernel_launch(void* const* d_in, const int* in_sizes, int n_in,
                              void* d_out, int out_size) {
    const float* feat   = (const float*)d_in[0];
    const int*   src    = (const int*)  d_in[1];
    const int*   dst    = (const int*)  d_in[2];
    const float* ew     = (const float*)d_in[3];
    const float* weight = (const float*)d_in[4];
    const float* bias   = (const float*)d_in[5];
    const float* maskr  = (const float*)d_in[6];
    float* out = (float*)d_out;

    k_init<<<256, 256>>>();
    k_deg<<<(EE + 255) / 256, 256>>>(src, dst);
    k_scan1<<<NB_SCAN, 1024>>>();
    k_scan2<<<1, 128>>>();
    k_scan3<<<(NN + 255) / 256, 256>>>();
    k_bucket<<<(EE + 255) / 256, 256>>>(src, dst, ew);
    k_wt<<<(KOUT * KIN + 255) / 256, 256>>>(weight, maskr);
    k_gemm_mma<<<(NN + 127) / 128, 256>>>(feat);
    k_agg<<<(NN + 7) / 8, 256>>>(out, bias);
}

// round 11
// speedup vs baseline: 1.9715x; 1.1482x over previous
#include <cuda_runtime.h>
#include <cuda_bf16.h>
#include <cstdint>

#define NN   100000
#define EE   1600000
#define KIN  256
#define KOUT 128
#define NB_SCAN ((NN + 1023) / 1024)   // 98

// Scratch (allocation-free rule: __device__ globals)
__device__ float  g_featproj[NN * KOUT];   // 51.2 MB projected features
__device__ float2 g_edges[EE];             // dst-bucketed (src_bits, weight)
__device__ int    g_outcnt[NN];
__device__ int    g_incnt[NN];
__device__ int    g_scanpart[NN];
__device__ int    g_rowoff[NN + 1];
__device__ int    g_cursor[NN];
__device__ int    g_blocksum[NB_SCAN];
__device__ int    g_blockoff[NB_SCAN];
__device__ __nv_bfloat16 g_wt_hi[KOUT * KIN];   // W^T hi  [N=128][K=256]
__device__ __nv_bfloat16 g_wt_lo[KOUT * KIN];   // W^T lo

// ---------------------------------------------------------------------------
__global__ void k_init() {
    int i = blockIdx.x * blockDim.x + threadIdx.x;
    int stride = gridDim.x * blockDim.x;
    for (int j = i; j < NN; j += stride) { g_outcnt[j] = 0; g_incnt[j] = 0; }
    if (i == 0) g_rowoff[NN] = EE;
}

// ---------------------------------------------------------------------------
__global__ void k_deg(const int* __restrict__ src, const int* __restrict__ dst) {
    int i = blockIdx.x * blockDim.x + threadIdx.x;
    if (i < EE) {
        atomicAdd(&g_outcnt[src[i]], 1);
        atomicAdd(&g_incnt[dst[i]], 1);
    }
}

// ---------------------------------------------------------------------------
// Exclusive scan of in-degrees (3 kernels)
// ---------------------------------------------------------------------------
__device__ __forceinline__ int warpInclScan(int v) {
#pragma unroll
    for (int o = 1; o < 32; o <<= 1) {
        int n = __shfl_up_sync(0xFFFFFFFFu, v, o);
        if ((threadIdx.x & 31) >= o) v += n;
    }
    return v;
}

__global__ __launch_bounds__(1024) void k_scan1() {
    __shared__ int ws[32];
    int tid = threadIdx.x;
    int i = blockIdx.x * 1024 + tid;
    int lane = tid & 31, wid = tid >> 5;
    int v = (i < NN) ? g_incnt[i] : 0;
    int inc = warpInclScan(v);
    if (lane == 31) ws[wid] = inc;
    __syncthreads();
    if (wid == 0) ws[lane] = warpInclScan(ws[lane]);
    __syncthreads();
    int excl = inc - v + (wid > 0 ? ws[wid - 1] : 0);
    if (i < NN) g_scanpart[i] = excl;
    if (tid == 1023) g_blocksum[blockIdx.x] = ws[31];
}

__global__ __launch_bounds__(128) void k_scan2() {
    __shared__ int ws[4];
    int tid = threadIdx.x;
    int lane = tid & 31, wid = tid >> 5;
    int v = (tid < NB_SCAN) ? g_blocksum[tid] : 0;
    int inc = warpInclScan(v);
    if (lane == 31) ws[wid] = inc;
    __syncthreads();
    if (wid == 0) {
        int w = (lane < 4) ? ws[lane] : 0;   // full warp runs the shfl scan
        w = warpInclScan(w);
        if (lane < 4) ws[lane] = w;
    }
    __syncthreads();
    int excl = inc - v + (wid > 0 ? ws[wid - 1] : 0);
    if (tid < NB_SCAN) g_blockoff[tid] = excl;
}

__global__ void k_scan3() {
    int i = blockIdx.x * blockDim.x + threadIdx.x;
    if (i < NN) {
        int off = g_scanpart[i] + g_blockoff[i >> 10];
        g_rowoff[i] = off;
        g_cursor[i] = off;
    }
}

// ---------------------------------------------------------------------------
__global__ void k_bucket(const int* __restrict__ src, const int* __restrict__ dst,
                         const float* __restrict__ ew) {
    int e = blockIdx.x * blockDim.x + threadIdx.x;
    if (e < EE) {
        int d = dst[e];
        int pos = atomicAdd(&g_cursor[d], 1);
        g_edges[pos] = make_float2(__int_as_float(src[e]), ew[e]);
    }
}

// ---------------------------------------------------------------------------
// Kernel: transpose + mask + bf16 trunc-hi/lo split of weight: W[K,N]->Wt[N,K]
// ---------------------------------------------------------------------------
__global__ void k_wt(const float* __restrict__ weight, const float* __restrict__ maskr) {
    int i = blockIdx.x * blockDim.x + threadIdx.x;
    if (i >= KOUT * KIN) return;
    int n = i >> 8;          // 0..127
    int k = i & 255;         // 0..255
    float v = (maskr[k * KOUT + n] > 0.5f) ? weight[k * KOUT + n] : 0.f;
    uint32_t u = __float_as_uint(v);
    uint32_t hi_bits = u & 0xFFFF0000u;                 // truncation hi
    float lo = v - __uint_as_float(hi_bits);
    g_wt_hi[i] = __ushort_as_bfloat16((unsigned short)(hi_bits >> 16));
    g_wt_lo[i] = __float2bfloat16(lo);
}

// ---------------------------------------------------------------------------
// bf16-split tensor-core GEMM on mma.sync (HMMA).
// featproj = diag(out_deg^-1/2) * (feat @ maskedW), scale applied in EPILOGUE.
// A split: trunc-hi (PRMT pack) + RN lo of remainder — cheap convert path.
// BM=128, BN=128, BK=32; 8 warps, warp tile 32x64 (2x8 m16n8k16 tiles).
// ---------------------------------------------------------------------------
#define SSTR 40

__device__ __forceinline__ uint32_t smem_u32(const void* p) {
    uint32_t a;
    asm("{ .reg .u64 t; cvta.to.shared.u64 t, %1; cvt.u32.u64 %0, t; }"
        : "=r"(a) : "l"(p));
    return a;
}

__device__ __forceinline__ void ldm_x4(uint32_t* r, uint32_t addr) {
    asm volatile("ldmatrix.sync.aligned.m8n8.x4.shared.b16 {%0,%1,%2,%3}, [%4];"
                 : "=r"(r[0]), "=r"(r[1]), "=r"(r[2]), "=r"(r[3]) : "r"(addr));
}

__device__ __forceinline__ void mma_bf16(float* c, const uint32_t* a, const uint32_t* b) {
    asm volatile(
        "mma.sync.aligned.m16n8k16.row.col.f32.bf16.bf16.f32 "
        "{%0,%1,%2,%3}, {%4,%5,%6,%7}, {%8,%9}, {%0,%1,%2,%3};"
        : "+f"(c[0]), "+f"(c[1]), "+f"(c[2]), "+f"(c[3])
        : "r"(a[0]), "r"(a[1]), "r"(a[2]), "r"(a[3]), "r"(b[0]), "r"(b[1]));
}

// split one pair of floats: packed trunc-hi bf16x2 + packed RN-lo bf16x2
__device__ __forceinline__ void split2(float f0, float f1,
                                       uint32_t& hi2, uint32_t& lo2) {
    uint32_t u0 = __float_as_uint(f0), u1 = __float_as_uint(f1);
    hi2 = __byte_perm(u0, u1, 0x7632);                  // {u0.hi16, u1.hi16}
    float l0 = f0 - __uint_as_float(u0 & 0xFFFF0000u);  // FADD w/ negate mod
    float l1 = f1 - __uint_as_float(u1 & 0xFFFF0000u);
    __nv_bfloat162 l = __floats2bfloat162_rn(l0, l1);   // one packed cvt
    lo2 = *reinterpret_cast<uint32_t*>(&l);
}

__global__ __launch_bounds__(256) void k_gemm_mma(const float* __restrict__ feat) {
    __shared__ __nv_bfloat16 sAhi[128 * SSTR];
    __shared__ __nv_bfloat16 sAlo[128 * SSTR];
    __shared__ __nv_bfloat16 sBhi[128 * SSTR];
    __shared__ __nv_bfloat16 sBlo[128 * SSTR];
    __shared__ float sscale[128];

    const int tid = threadIdx.x;
    const int wid = tid >> 5, lane = tid & 31;
    const int blockRow = blockIdx.x * 128;

    if (tid < 128) {
        int r = blockRow + tid;
        sscale[tid] = (r < NN) ? rsqrtf((float)max(g_outcnt[r], 1)) : 0.f;
    }
    __syncthreads();

    const uint32_t uAhi = smem_u32(sAhi), uAlo = smem_u32(sAlo);
    const uint32_t uBhi = smem_u32(sBhi), uBlo = smem_u32(sBlo);

    const int mbase = (wid & 3) * 32;
    const int nbase = (wid >> 2) * 64;

    float acc[2][8][4];
#pragma unroll
    for (int m = 0; m < 2; m++)
#pragma unroll
        for (int n = 0; n < 8; n++)
#pragma unroll
            for (int q = 0; q < 4; q++) acc[m][n][q] = 0.f;

    const uint32_t aoff = (uint32_t)((lane & 15) * (SSTR * 2) + (lane >> 4) * 16);
    const uint32_t boff = (uint32_t)(((lane & 7) + ((lane >> 4) << 3)) * (SSTR * 2) +
                                     (((lane >> 3) & 1) << 4));

    for (int c = 0; c < 8; c++) {
        const int k0 = c * 32;

        // ---- A: 128 rows x 32 cols fp32 -> trunc-hi/lo bf16 (UNSCALED)
        {
            int row = tid >> 1;
            int ch = (tid & 1) * 16;
            int gr = blockRow + row;
            const float4* fp = (gr < NN)
                ? reinterpret_cast<const float4*>(&feat[gr * KIN + k0 + ch]) : nullptr;
#pragma unroll
            for (int j = 0; j < 4; j++) {
                float4 a = fp ? fp[j] : make_float4(0.f, 0.f, 0.f, 0.f);
                uint32_t h01, l01, h23, l23;
                split2(a.x, a.y, h01, l01);
                split2(a.z, a.w, h23, l23);
                int o = row * SSTR + ch + j * 4;
                *reinterpret_cast<uint2*>(&sAhi[o]) = make_uint2(h01, h23);
                *reinterpret_cast<uint2*>(&sAlo[o]) = make_uint2(l01, l23);
            }
        }
        // ---- B: Wt[n][k0..k0+31] hi/lo
        {
            int row = tid >> 1;
            int q = (tid & 1) * 2;
            uint4 h0 = *reinterpret_cast<const uint4*>(&g_wt_hi[row * KIN + k0 + q * 8]);
            uint4 h1 = *reinterpret_cast<const uint4*>(&g_wt_hi[row * KIN + k0 + (q + 1) * 8]);
            uint4 l0 = *reinterpret_cast<const uint4*>(&g_wt_lo[row * KIN + k0 + q * 8]);
            uint4 l1 = *reinterpret_cast<const uint4*>(&g_wt_lo[row * KIN + k0 + (q + 1) * 8]);
            int o = row * SSTR + q * 8;
            *reinterpret_cast<uint4*>(&sBhi[o])     = h0;
            *reinterpret_cast<uint4*>(&sBhi[o + 8]) = h1;
            *reinterpret_cast<uint4*>(&sBlo[o])     = l0;
            *reinterpret_cast<uint4*>(&sBlo[o + 8]) = l1;
        }
        __syncthreads();

#pragma unroll
        for (int ks = 0; ks < 2; ks++) {
            const uint32_t kb = (uint32_t)(ks * 16 * 2);

            uint32_t ahi[2][4], alo[2][4];
#pragma unroll
            for (int mt = 0; mt < 2; mt++) {
                uint32_t ab = (uint32_t)((mbase + mt * 16) * (SSTR * 2)) + kb + aoff;
                ldm_x4(ahi[mt], uAhi + ab);
                ldm_x4(alo[mt], uAlo + ab);
            }
            uint32_t bhi[8][2], blo[8][2];
#pragma unroll
            for (int p = 0; p < 4; p++) {
                uint32_t bb = (uint32_t)((nbase + p * 16) * (SSTR * 2)) + kb + boff;
                uint32_t r[4];
                ldm_x4(r, uBhi + bb);
                bhi[2 * p][0] = r[0]; bhi[2 * p][1] = r[1];
                bhi[2 * p + 1][0] = r[2]; bhi[2 * p + 1][1] = r[3];
                ldm_x4(r, uBlo + bb);
                blo[2 * p][0] = r[0]; blo[2 * p][1] = r[1];
                blo[2 * p + 1][0] = r[2]; blo[2 * p + 1][1] = r[3];
            }
#pragma unroll
            for (int mt = 0; mt < 2; mt++)
#pragma unroll
                for (int nt = 0; nt < 8; nt++) {
                    mma_bf16(acc[mt][nt], ahi[mt], bhi[nt]);
                    mma_bf16(acc[mt][nt], ahi[mt], blo[nt]);
                    mma_bf16(acc[mt][nt], alo[mt], bhi[nt]);
                }
        }
        __syncthreads();
    }

    // Epilogue: apply out-degree scale here (exact in fp32), then store.
#pragma unroll
    for (int mt = 0; mt < 2; mt++) {
        int lr0 = mbase + mt * 16 + (lane >> 2);
        int lr1 = lr0 + 8;
        float s0 = sscale[lr0], s1 = sscale[lr1];
        int r0 = blockRow + lr0, r1 = blockRow + lr1;
#pragma unroll
        for (int nt = 0; nt < 8; nt++) {
            int col = nbase + nt * 8 + (lane & 3) * 2;
            if (r0 < NN)
                *reinterpret_cast<float2*>(&g_featproj[r0 * KOUT + col]) =
                    make_float2(acc[mt][nt][0] * s0, acc[mt][nt][1] * s0);
            if (r1 < NN)
                *reinterpret_cast<float2*>(&g_featproj[r1 * KOUT + col]) =
                    make_float2(acc[mt][nt][2] * s1, acc[mt][nt][3] * s1);
        }
    }
}

// ---------------------------------------------------------------------------
// Kernel: aggregation. One warp per dst node, atomic-free, fused finalize.
// ---------------------------------------------------------------------------
__global__ __launch_bounds__(256) void k_agg(float* __restrict__ out,
                                             const float* __restrict__ bias) {
    int node = blockIdx.x * 8 + (threadIdx.x >> 5);
    int lane = threadIdx.x & 31;
    if (node >= NN) return;

    int beg = g_rowoff[node];
    int end = g_rowoff[node + 1];

    float4 acc = make_float4(0.f, 0.f, 0.f, 0.f);
    int e = beg;
    for (; e + 1 < end; e += 2) {
        float2 e0 = g_edges[e];
        float2 e1 = g_edges[e + 1];
        int s0 = __float_as_int(e0.x);
        int s1 = __float_as_int(e1.x);
        float4 v0 = *reinterpret_cast<const float4*>(&g_featproj[s0 * KOUT + lane * 4]);
        float4 v1 = *reinterpret_cast<const float4*>(&g_featproj[s1 * KOUT + lane * 4]);
        acc.x = fmaf(e0.y, v0.x, fmaf(e1.y, v1.x, acc.x));
        acc.y = fmaf(e0.y, v0.y, fmaf(e1.y, v1.y, acc.y));
        acc.z = fmaf(e0.y, v0.z, fmaf(e1.y, v1.z, acc.z));
        acc.w = fmaf(e0.y, v0.w, fmaf(e1.y, v1.w, acc.w));
    }
    if (e < end) {
        float2 e0 = g_edges[e];
        int s0 = __float_as_int(e0.x);
        float4 v0 = *reinterpret_cast<const float4*>(&g_featproj[s0 * KOUT + lane * 4]);
        acc.x = fmaf(e0.y, v0.x, acc.x);
        acc.y = fmaf(e0.y, v0.y, acc.y);
        acc.z = fmaf(e0.y, v0.z, acc.z);
        acc.w = fmaf(e0.y, v0.w, acc.w);
    }

    float sc = rsqrtf((float)max(end - beg, 1));
    float4 b = *reinterpret_cast<const float4*>(&bias[lane * 4]);
    acc.x = fmaf(acc.x, sc, b.x);
    acc.y = fmaf(acc.y, sc, b.y);
    acc.z = fmaf(acc.z, sc, b.z);
    acc.w = fmaf(acc.w, sc, b.w);
    *reinterpret_cast<float4*>(&out[node * KOUT + lane * 4]) = acc;
}

// ---------------------------------------------------------------------------
// Fork-join: side stream runs {wt, gemm} concurrently with {scans, bucket}.
// Streams/events created once (host resources only; no device memory).
// ---------------------------------------------------------------------------
static cudaStream_t s_side = 0;
static cudaEvent_t  s_eDeg = 0, s_eGemm = 0;

extern "C" void kernel_launch(void* const* d_in, const int* in_sizes, int n_in,
                              void* d_out, int out_size) {
    const float* feat   = (const float*)d_in[0];
    const int*   src    = (const int*)  d_in[1];
    const int*   dst    = (const int*)  d_in[2];
    const float* ew     = (const float*)d_in[3];
    const float* weight = (const float*)d_in[4];
    const float* bias   = (const float*)d_in[5];
    const float* maskr  = (const float*)d_in[6];
    float* out = (float*)d_out;

    if (!s_side) {
        cudaStreamCreateWithFlags(&s_side, cudaStreamNonBlocking);
        cudaEventCreateWithFlags(&s_eDeg, cudaEventDisableTiming);
        cudaEventCreateWithFlags(&s_eGemm, cudaEventDisableTiming);
    }

    // main stream: init + degrees
    k_init<<<256, 256>>>();
    k_deg<<<(EE + 255) / 256, 256>>>(src, dst);
    cudaEventRecord(s_eDeg, 0);

    // side stream: weight split + GEMM (needs outcnt)
    cudaStreamWaitEvent(s_side, s_eDeg, 0);
    k_wt<<<(KOUT * KIN + 255) / 256, 256, 0, s_side>>>(weight, maskr);
    k_gemm_mma<<<(NN + 127) / 128, 256, 0, s_side>>>(feat);
    cudaEventRecord(s_eGemm, s_side);

    // main stream: CSR build (needs incnt)
    k_scan1<<<NB_SCAN, 1024>>>();
    k_scan2<<<1, 128>>>();
    k_scan3<<<(NN + 255) / 256, 256>>>();
    k_bucket<<<(EE + 255) / 256, 256>>>(src, dst, ew);

    // join, then aggregate
    cudaStreamWaitEvent(0, s_eGemm, 0);
    k_agg<<<(NN + 7) / 8, 256>>>(out, bias);
}